// round 6
// baseline (speedup 1.0000x reference)
#include <cuda_runtime.h>
#include <cuda_fp16.h>
#include <cstdint>

#define BATCH 2048
#define NTOK 64
#define DIM 512
#define HEADS 16
#define QKV 1536
#define MTOT (BATCH * NTOK)      // 131072 rows

// ---------------------------------------------------------------------------
// Scratch (static __device__ globals; no allocations allowed)
// ---------------------------------------------------------------------------
__device__ __half g_xh[(size_t)MTOT * DIM];      // 134 MB: x in fp16
__device__ __half g_qkvh[(size_t)MTOT * QKV];    // 403 MB: qkv (fp16)
__device__ __half g_attnh[(size_t)MTOT * DIM];   // 134 MB: attention out (fp16)
__device__ __half g_wqkvth[QKV * DIM];           // w_qkv^T  [1536][512] fp16
__device__ __half g_wprojth[DIM * DIM];          // w_proj^T [512][512] fp16
__device__ float g_Kss[NTOK * NTOK];             // gaussian * softmax scale

// ---------------------------------------------------------------------------
// PTX helpers
// ---------------------------------------------------------------------------
__device__ __forceinline__ uint32_t smem_u32(const void* p) {
    uint32_t a;
    asm("{ .reg .u64 t; cvta.to.shared.u64 t, %1; cvt.u32.u64 %0, t; }"
        : "=r"(a) : "l"(p));
    return a;
}

__device__ __forceinline__ void cp16(uint32_t dst, const void* src) {
    asm volatile("cp.async.cg.shared.global [%0], [%1], 16;"
                 :: "r"(dst), "l"(src));
}
#define CP_COMMIT() asm volatile("cp.async.commit_group;")
#define CP_WAIT(N) asm volatile("cp.async.wait_group %0;" :: "n"(N))

#define LDSM_X4(R0, R1, R2, R3, ADDR) \
    asm volatile("ldmatrix.sync.aligned.m8n8.x4.shared.b16 {%0,%1,%2,%3}, [%4];" \
                 : "=r"(R0), "=r"(R1), "=r"(R2), "=r"(R3) : "r"(ADDR))
#define LDSM_X4_T(R0, R1, R2, R3, ADDR) \
    asm volatile("ldmatrix.sync.aligned.m8n8.x4.trans.shared.b16 {%0,%1,%2,%3}, [%4];" \
                 : "=r"(R0), "=r"(R1), "=r"(R2), "=r"(R3) : "r"(ADDR))

__device__ __forceinline__ void mma16816(float c[4], const uint32_t a[4],
                                         uint32_t b0, uint32_t b1) {
    asm volatile(
        "mma.sync.aligned.m16n8k16.row.col.f32.f16.f16.f32 "
        "{%0,%1,%2,%3}, {%4,%5,%6,%7}, {%8,%9}, {%0,%1,%2,%3};"
        : "+f"(c[0]), "+f"(c[1]), "+f"(c[2]), "+f"(c[3])
        : "r"(a[0]), "r"(a[1]), "r"(a[2]), "r"(a[3]), "r"(b0), "r"(b1));
}

// ---------------------------------------------------------------------------
// Kss precompute: row-normalised gaussian * HEAD_DIM^-0.5
// ---------------------------------------------------------------------------
__global__ void init_kss_kernel() {
    const int i = threadIdx.x;  // 0..63
    const float yi = (float)(i >> 3), xi = (float)(i & 7);
    const float inv2s2 = 1.0f / (2.0f * 0.39f * 0.39f);
    float row[64];
    float s = 0.f;
#pragma unroll
    for (int j = 0; j < 64; ++j) {
        float dy = yi - (float)(j >> 3);
        float dx = xi - (float)(j & 7);
        float e = __expf(-(dy * dy + dx * dx) * inv2s2);
        row[j] = e;
        s += e;
    }
    const float inv = 0.17677669529663688f / s;  // scale / rowsum
#pragma unroll
    for (int j = 0; j < 64; ++j) g_Kss[i * 64 + j] = row[j] * inv;
}

// ---------------------------------------------------------------------------
// x fp32 -> fp16
// ---------------------------------------------------------------------------
__global__ void cvt_x_kernel(const float* __restrict__ x) {
    const size_t i = ((size_t)blockIdx.x * 256 + threadIdx.x) * 8;
    float4 a = *(const float4*)(x + i);
    float4 b = *(const float4*)(x + i + 4);
    __half h[8];
    h[0] = __float2half_rn(a.x); h[1] = __float2half_rn(a.y);
    h[2] = __float2half_rn(a.z); h[3] = __float2half_rn(a.w);
    h[4] = __float2half_rn(b.x); h[5] = __float2half_rn(b.y);
    h[6] = __float2half_rn(b.z); h[7] = __float2half_rn(b.w);
    *(uint4*)(&g_xh[i]) = *(uint4*)h;
}

// ---------------------------------------------------------------------------
// Weight transpose + fp16 convert: dst[n][k] = h(src[k][n]); K = 512
// ---------------------------------------------------------------------------
template <int MODE>
__global__ void transpose_cvt_kernel(const float* __restrict__ src) {
    constexpr int N = (MODE == 0) ? QKV : DIM;
    __half* __restrict__ dst = (MODE == 0) ? (__half*)g_wqkvth : (__half*)g_wprojth;
    __shared__ float t[32][33];
    const int bx = blockIdx.x * 32;  // n
    const int by = blockIdx.y * 32;  // k
    const int x = threadIdx.x, y = threadIdx.y;  // 32 x 8
#pragma unroll
    for (int i = 0; i < 32; i += 8)
        t[y + i][x] = src[(size_t)(by + y + i) * N + bx + x];
    __syncthreads();
#pragma unroll
    for (int i = 0; i < 32; i += 8)
        dst[(size_t)(bx + y + i) * 512 + by + x] = __float2half_rn(t[x][y + i]);
}

// ---------------------------------------------------------------------------
// fp16 GEMM: C[M, N] = A[M, 512] @ Bt[N, 512]^T + bias
// CTA 128x256, 256 thr = 8 warps (2m x 4n), warp tile 64x64, k-tile 64,
// cp.async double-buffered, ldmatrix fragments, occ-1.
// MODE 0: A=g_xh,    C=g_qkvh (fp16), N=1536
// MODE 1: A=g_attnh, C=out (fp32),    N=512
// smem: A0@0 (18432B), B0@18432 (36864B), A1@55296, B1@73728 -> 110592B
// ---------------------------------------------------------------------------
#define GSM_TOTAL 110592

template <int MODE>
__global__ void __launch_bounds__(256, 1) gemm_h_kernel(
    const float* __restrict__ bias, float* __restrict__ CoutF) {
    constexpr int N = (MODE == 0) ? QKV : DIM;
    const __half* __restrict__ A = (MODE == 0) ? (const __half*)g_xh
                                               : (const __half*)g_attnh;
    const __half* __restrict__ Bt = (MODE == 0) ? (const __half*)g_wqkvth
                                                : (const __half*)g_wprojth;

    extern __shared__ char sm[];
    const uint32_t sb = smem_u32(sm);
    const int tid = threadIdx.x;
    const int lane = tid & 31;
    const int wid = tid >> 5;
    const int wm = wid & 1;   // 0..1 -> m offset wm*64
    const int wn = wid >> 1;  // 0..3 -> n offset wn*64

    const int brow = blockIdx.y * 128;
    const int bcol = blockIdx.x * 256;

    // loader: 8 lanes per 128B (kt-slice) row
    const int lr = tid >> 3;       // 0..31
    const int lc = tid & 7;        // 16B chunk
    const char* Abase = (const char*)(A + (size_t)(brow + lr) * 512) + lc * 16;
    const char* Bbase = (const char*)(Bt + (size_t)(bcol + lr) * 512) + lc * 16;
    const uint32_t sA[2] = {sb + 0, sb + 55296};
    const uint32_t sB[2] = {sb + 18432, sb + 73728};
    const uint32_t dstoff = (uint32_t)(lr * 144 + lc * 16);

    float c[4][8][4];
#pragma unroll
    for (int mt = 0; mt < 4; ++mt)
#pragma unroll
        for (int nt = 0; nt < 8; ++nt)
#pragma unroll
            for (int e = 0; e < 4; ++e) c[mt][nt][e] = 0.f;

#define LOAD_TILE(KT, BUF) do { \
    _Pragma("unroll") \
    for (int it = 0; it < 4; ++it) \
        cp16(sA[BUF] + dstoff + it * 32 * 144, Abase + (size_t)it * 32 * 1024 + (KT) * 128); \
    _Pragma("unroll") \
    for (int it = 0; it < 8; ++it) \
        cp16(sB[BUF] + dstoff + it * 32 * 144, Bbase + (size_t)it * 32 * 1024 + (KT) * 128); \
    CP_COMMIT(); \
} while (0)

    LOAD_TILE(0, 0);
    LOAD_TILE(1, 1);

#pragma unroll 1
    for (int kt = 0; kt < 8; ++kt) {
        const int buf = kt & 1;
        if (kt < 7) { CP_WAIT(1); } else { CP_WAIT(0); }
        __syncthreads();
#pragma unroll
        for (int kk = 0; kk < 4; ++kk) {
            uint32_t a[4][4], b[4][4];
#pragma unroll
            for (int mt = 0; mt < 4; ++mt) {
                const uint32_t addr = sA[buf] + (wm * 64 + mt * 16 + (lane & 15)) * 144 +
                                      kk * 32 + (lane >> 4) * 16;
                LDSM_X4(a[mt][0], a[mt][1], a[mt][2], a[mt][3], addr);
            }
#pragma unroll
            for (int nb = 0; nb < 4; ++nb) {
                const uint32_t addr = sB[buf] + (wn * 64 + nb * 16 + (lane & 15)) * 144 +
                                      kk * 32 + (lane >> 4) * 16;
                LDSM_X4(b[nb][0], b[nb][1], b[nb][2], b[nb][3], addr);
            }
#pragma unroll
            for (int mt = 0; mt < 4; ++mt)
#pragma unroll
                for (int nt = 0; nt < 8; ++nt)
                    mma16816(c[mt][nt], a[mt], b[nt >> 1][nt & 1],
                             b[nt >> 1][2 + (nt & 1)]);
        }
        __syncthreads();
        if (kt + 2 < 8) LOAD_TILE(kt + 2, buf);
    }
    __syncthreads();

    const int g = lane >> 2, t4 = lane & 3;

    if (MODE == 0) {
        // one-pass fp16 epilogue: bias add in fp32, convert, stage, copy
        __half* es = (__half*)sm;  // 128 x 264 halves (528B row stride)
#pragma unroll
        for (int mt = 0; mt < 4; ++mt) {
            const int r0 = wm * 64 + mt * 16 + g;
#pragma unroll
            for (int nt = 0; nt < 8; ++nt) {
                const int c0 = wn * 64 + nt * 8 + 2 * t4;
                const float2 bv = *(const float2*)(bias + bcol + c0);
                *(half2*)((char*)es + r0 * 528 + c0 * 2) =
                    __floats2half2_rn(c[mt][nt][0] + bv.x, c[mt][nt][1] + bv.y);
                *(half2*)((char*)es + (r0 + 8) * 528 + c0 * 2) =
                    __floats2half2_rn(c[mt][nt][2] + bv.x, c[mt][nt][3] + bv.y);
            }
        }
        __syncthreads();
        // copy out: 128 rows x 512B; 4096 chunks of 16B, 16 per thread
#pragma unroll
        for (int it = 0; it < 16; ++it) {
            const int idx = tid + it * 256;
            const int row = idx >> 5;
            const int ch = idx & 31;
            uint4 v = *(uint4*)((char*)es + row * 528 + ch * 16);
            *(uint4*)((char*)(g_qkvh + (size_t)(brow + row) * QKV + bcol) + ch * 16) = v;
        }
    } else {
        // two-pass fp32 epilogue (halves of 128 cols)
        float* es = (float*)sm;  // 128 x 132 floats
#pragma unroll
        for (int h = 0; h < 2; ++h) {
            if ((wn >> 1) == h) {
#pragma unroll
                for (int mt = 0; mt < 4; ++mt) {
                    const int r0 = wm * 64 + mt * 16 + g;
#pragma unroll
                    for (int nt = 0; nt < 8; ++nt) {
                        const int c0 = (wn & 1) * 64 + nt * 8 + 2 * t4;
                        *(float2*)&es[r0 * 132 + c0] =
                            make_float2(c[mt][nt][0], c[mt][nt][1]);
                        *(float2*)&es[(r0 + 8) * 132 + c0] =
                            make_float2(c[mt][nt][2], c[mt][nt][3]);
                    }
                }
            }
            __syncthreads();
            const int cb = (tid & 31) * 4;
            const float4 bv = *(const float4*)(bias + bcol + h * 128 + cb);
#pragma unroll
            for (int it = 0; it < 16; ++it) {
                const int row = (tid >> 5) + it * 8;
                float4 o;
                o.x = es[row * 132 + cb + 0] + bv.x;
                o.y = es[row * 132 + cb + 1] + bv.y;
                o.z = es[row * 132 + cb + 2] + bv.z;
                o.w = es[row * 132 + cb + 3] + bv.w;
                *(float4*)(CoutF + (size_t)(brow + row) * DIM + bcol + h * 128 + cb) = o;
            }
            __syncthreads();
        }
    }
#undef LOAD_TILE
}

// ---------------------------------------------------------------------------
// Attention: one CTA per (b, h). 128 thr = 4 warps, warp owns 16 query rows.
// fp16 mma.m16n8k16 for S = Q K^T and O = P V; V consumed via ldmatrix.trans.
// ---------------------------------------------------------------------------
__global__ void __launch_bounds__(128) attn_kernel() {
    __shared__ __half qs[64 * 40];   // stride 40 halves = 80B
    __shared__ __half ks[64 * 40];
    __shared__ __half vsm[64 * 40];
    __shared__ __half ps[64 * 72];   // stride 72 halves = 144B

    const int bid = blockIdx.x;
    const int b = bid >> 4;
    const int h = bid & 15;
    const int tid = threadIdx.x;
    const int lane = tid & 31;
    const int wid = tid >> 5;
    const int g = lane >> 2;
    const int t = lane & 3;
    const size_t rowbase = (size_t)b * 64;

    const uint32_t qs_u = smem_u32(qs);
    const uint32_t ks_u = smem_u32(ks);
    const uint32_t vs_u = smem_u32(vsm);
    const uint32_t ps_u = smem_u32(ps);

    // ---- load Q, K, V (64 x 32 fp16 each) ----
#pragma unroll
    for (int it = 0; it < 2; ++it) {
        const int idx = tid + it * 128;
        const int row = idx >> 2;
        const int ch = idx & 3;
        const char* src = (const char*)(g_qkvh + (rowbase + row) * QKV + h * 32) + ch * 16;
        *(uint4*)((char*)qs + row * 80 + ch * 16) = *(const uint4*)(src);
        *(uint4*)((char*)ks + row * 80 + ch * 16) = *(const uint4*)(src + 512 * 2);
        *(uint4*)((char*)vsm + row * 80 + ch * 16) = *(const uint4*)(src + 1024 * 2);
    }
    __syncthreads();

    const int m0 = wid * 16;

    // ---- S = Q K^T : warp 16 x 64, K=32 ----
    float s[8][4];
#pragma unroll
    for (int nt = 0; nt < 8; ++nt)
#pragma unroll
        for (int e = 0; e < 4; ++e) s[nt][e] = 0.f;

#pragma unroll
    for (int kk = 0; kk < 2; ++kk) {
        uint32_t a[4];
        LDSM_X4(a[0], a[1], a[2], a[3],
                qs_u + (m0 + (lane & 15)) * 80 + kk * 32 + (lane >> 4) * 16);
#pragma unroll
        for (int nb = 0; nb < 4; ++nb) {
            uint32_t bb[4];
            LDSM_X4(bb[0], bb[1], bb[2], bb[3],
                    ks_u + (nb * 16 + (lane & 15)) * 80 + kk * 32 + (lane >> 4) * 16);
            mma16816(s[nb * 2], a, bb[0], bb[2]);
            mma16816(s[nb * 2 + 1], a, bb[1], bb[3]);
        }
    }

    // ---- gaussian mask (includes scale) + softmax ----
    const int iA = m0 + g;
    const int iB = m0 + g + 8;
    float mA = -1e30f, mB = -1e30f;
#pragma unroll
    for (int nt = 0; nt < 8; ++nt) {
        const int j0 = nt * 8 + 2 * t;
        const float2 kA = *(const float2*)(g_Kss + iA * 64 + j0);
        const float2 kB = *(const float2*)(g_Kss + iB * 64 + j0);
        s[nt][0] *= kA.x;
        s[nt][1] *= kA.y;
        s[nt][2] *= kB.x;
        s[nt][3] *= kB.y;
        mA = fmaxf(mA, fmaxf(s[nt][0], s[nt][1]));
        mB = fmaxf(mB, fmaxf(s[nt][2], s[nt][3]));
    }
    mA = fmaxf(mA, __shfl_xor_sync(0xffffffffu, mA, 1));
    mA = fmaxf(mA, __shfl_xor_sync(0xffffffffu, mA, 2));
    mB = fmaxf(mB, __shfl_xor_sync(0xffffffffu, mB, 1));
    mB = fmaxf(mB, __shfl_xor_sync(0xffffffffu, mB, 2));

    float sA = 0.f, sB = 0.f;
#pragma unroll
    for (int nt = 0; nt < 8; ++nt) {
        s[nt][0] = __expf(s[nt][0] - mA);
        s[nt][1] = __expf(s[nt][1] - mA);
        s[nt][2] = __expf(s[nt][2] - mB);
        s[nt][3] = __expf(s[nt][3] - mB);
        sA += s[nt][0] + s[nt][1];
        sB += s[nt][2] + s[nt][3];
    }
    sA += __shfl_xor_sync(0xffffffffu, sA, 1);
    sA += __shfl_xor_sync(0xffffffffu, sA, 2);
    sB += __shfl_xor_sync(0xffffffffu, sB, 1);
    sB += __shfl_xor_sync(0xffffffffu, sB, 2);
    const float rA = 1.0f / sA;
    const float rB = 1.0f / sB;

    // ---- P -> smem fp16 (warp-private rows) ----
#pragma unroll
    for (int nt = 0; nt < 8; ++nt) {
        const int j0 = nt * 8 + 2 * t;
        *(half2*)((char*)ps + iA * 144 + j0 * 2) =
            __floats2half2_rn(s[nt][0] * rA, s[nt][1] * rA);
        *(half2*)((char*)ps + iB * 144 + j0 * 2) =
            __floats2half2_rn(s[nt][2] * rB, s[nt][3] * rB);
    }
    __syncwarp();

    // ---- O = P V : warp 16 x 32, K=64 ----
    float o[4][4];
#pragma unroll
    for (int nt = 0; nt < 4; ++nt)
#pragma unroll
        for (int e = 0; e < 4; ++e) o[nt][e] = 0.f;

#pragma unroll
    for (int kk = 0; kk < 4; ++kk) {
        uint32_t a[4];
        LDSM_X4(a[0], a[1], a[2], a[3],
                ps_u + (m0 + (lane & 15)) * 144 + kk * 32 + (lane >> 4) * 16);
#pragma unroll
        for (int nb = 0; nb < 2; ++nb) {
            uint32_t bb[4];
            LDSM_X4_T(bb[0], bb[1], bb[2], bb[3],
                      vs_u + (kk * 16 + (lane & 15)) * 80 + nb * 32 + (lane >> 4) * 16);
            mma16816(o[nb * 2], a, bb[0], bb[1]);
            mma16816(o[nb * 2 + 1], a, bb[2], bb[3]);
        }
    }

    // ---- store O fp16 into g_attnh[b*64+row][h*32+col] ----
#pragma unroll
    for (int nt = 0; nt < 4; ++nt) {
        const int cc = h * 32 + nt * 8 + 2 * t;
        *(half2*)(g_attnh + (rowbase + iA) * 512 + cc) =
            __floats2half2_rn(o[nt][0], o[nt][1]);
        *(half2*)(g_attnh + (rowbase + iB) * 512 + cc) =
            __floats2half2_rn(o[nt][2], o[nt][3]);
    }
}

// ---------------------------------------------------------------------------
// Launch
// ---------------------------------------------------------------------------
extern "C" void kernel_launch(void* const* d_in, const int* in_sizes, int n_in,
                              void* d_out, int out_size) {
    (void)in_sizes;
    (void)n_in;
    (void)out_size;
    const float* x = (const float*)d_in[0];
    const float* w_qkv = (const float*)d_in[1];
    const float* b_qkv = (const float*)d_in[2];
    const float* w_proj = (const float*)d_in[3];
    const float* b_proj = (const float*)d_in[4];
    float* out = (float*)d_out;

    cudaFuncSetAttribute(gemm_h_kernel<0>,
                         cudaFuncAttributeMaxDynamicSharedMemorySize, GSM_TOTAL);
    cudaFuncSetAttribute(gemm_h_kernel<1>,
                         cudaFuncAttributeMaxDynamicSharedMemorySize, GSM_TOTAL);

    init_kss_kernel<<<1, 64>>>();
    cvt_x_kernel<<<MTOT * DIM / 8 / 256, 256>>>(x);
    transpose_cvt_kernel<0><<<dim3(QKV / 32, DIM / 32), dim3(32, 8)>>>(w_qkv);
    transpose_cvt_kernel<1><<<dim3(DIM / 32, DIM / 32), dim3(32, 8)>>>(w_proj);
    gemm_h_kernel<0><<<dim3(QKV / 256, MTOT / 128), 256, GSM_TOTAL>>>(b_qkv, nullptr);
    attn_kernel<<<BATCH * HEADS, 128>>>();
    gemm_h_kernel<1><<<dim3(DIM / 256, MTOT / 128), 256, GSM_TOTAL>>>(b_proj, out);
}

// round 7
// speedup vs baseline: 1.0417x; 1.0417x over previous
#include <cuda_runtime.h>
#include <cuda_fp16.h>
#include <cstdint>

#define BATCH 2048
#define NTOK 64
#define DIM 512
#define HEADS 16
#define QKV 1536
#define MTOT (BATCH * NTOK)      // 131072 rows

// ---------------------------------------------------------------------------
// Scratch (static __device__ globals; no allocations allowed)
// ---------------------------------------------------------------------------
__device__ __half g_xh[(size_t)MTOT * DIM];      // 134 MB: x in fp16
__device__ __half g_attnh[(size_t)MTOT * DIM];   // 134 MB: attention out (fp16)
__device__ __half g_wqkvth[QKV * DIM];           // w_qkv^T  [1536][512] fp16
__device__ __half g_wprojth[DIM * DIM];          // w_proj^T [512][512] fp16
__device__ float g_Kss[NTOK * NTOK];             // gaussian * softmax scale

// ---------------------------------------------------------------------------
// PTX helpers
// ---------------------------------------------------------------------------
__device__ __forceinline__ uint32_t smem_u32(const void* p) {
    uint32_t a;
    asm("{ .reg .u64 t; cvta.to.shared.u64 t, %1; cvt.u32.u64 %0, t; }"
        : "=r"(a) : "l"(p));
    return a;
}

__device__ __forceinline__ void cp16(uint32_t dst, const void* src) {
    asm volatile("cp.async.cg.shared.global [%0], [%1], 16;"
                 :: "r"(dst), "l"(src));
}
#define CP_COMMIT() asm volatile("cp.async.commit_group;")
#define CP_WAIT(N) asm volatile("cp.async.wait_group %0;" :: "n"(N))

#define LDSM_X4(R0, R1, R2, R3, ADDR) \
    asm volatile("ldmatrix.sync.aligned.m8n8.x4.shared.b16 {%0,%1,%2,%3}, [%4];" \
                 : "=r"(R0), "=r"(R1), "=r"(R2), "=r"(R3) : "r"(ADDR))
#define LDSM_X4_T(R0, R1, R2, R3, ADDR) \
    asm volatile("ldmatrix.sync.aligned.m8n8.x4.trans.shared.b16 {%0,%1,%2,%3}, [%4];" \
                 : "=r"(R0), "=r"(R1), "=r"(R2), "=r"(R3) : "r"(ADDR))

__device__ __forceinline__ void mma16816(float c[4], const uint32_t a[4],
                                         uint32_t b0, uint32_t b1) {
    asm volatile(
        "mma.sync.aligned.m16n8k16.row.col.f32.f16.f16.f32 "
        "{%0,%1,%2,%3}, {%4,%5,%6,%7}, {%8,%9}, {%0,%1,%2,%3};"
        : "+f"(c[0]), "+f"(c[1]), "+f"(c[2]), "+f"(c[3])
        : "r"(a[0]), "r"(a[1]), "r"(a[2]), "r"(a[3]), "r"(b0), "r"(b1));
}

__device__ __forceinline__ uint32_t pack_h2(float x, float y) {
    half2 h = __floats2half2_rn(x, y);
    return *(uint32_t*)&h;
}

// ---------------------------------------------------------------------------
// Kss precompute: row-normalised gaussian * HEAD_DIM^-0.5
// ---------------------------------------------------------------------------
__global__ void init_kss_kernel() {
    const int i = threadIdx.x;  // 0..63
    const float yi = (float)(i >> 3), xi = (float)(i & 7);
    const float inv2s2 = 1.0f / (2.0f * 0.39f * 0.39f);
    float row[64];
    float s = 0.f;
#pragma unroll
    for (int j = 0; j < 64; ++j) {
        float dy = yi - (float)(j >> 3);
        float dx = xi - (float)(j & 7);
        float e = __expf(-(dy * dy + dx * dx) * inv2s2);
        row[j] = e;
        s += e;
    }
    const float inv = 0.17677669529663688f / s;  // scale / rowsum
#pragma unroll
    for (int j = 0; j < 64; ++j) g_Kss[i * 64 + j] = row[j] * inv;
}

// ---------------------------------------------------------------------------
// x fp32 -> fp16
// ---------------------------------------------------------------------------
__global__ void cvt_x_kernel(const float* __restrict__ x) {
    const size_t i = ((size_t)blockIdx.x * 256 + threadIdx.x) * 8;
    float4 a = *(const float4*)(x + i);
    float4 b = *(const float4*)(x + i + 4);
    __half h[8];
    h[0] = __float2half_rn(a.x); h[1] = __float2half_rn(a.y);
    h[2] = __float2half_rn(a.z); h[3] = __float2half_rn(a.w);
    h[4] = __float2half_rn(b.x); h[5] = __float2half_rn(b.y);
    h[6] = __float2half_rn(b.z); h[7] = __float2half_rn(b.w);
    *(uint4*)(&g_xh[i]) = *(uint4*)h;
}

// ---------------------------------------------------------------------------
// Weight transpose + fp16 convert: dst[n][k] = h(src[k][n]); K = 512
// ---------------------------------------------------------------------------
template <int MODE>
__global__ void transpose_cvt_kernel(const float* __restrict__ src) {
    constexpr int N = (MODE == 0) ? QKV : DIM;
    __half* __restrict__ dst = (MODE == 0) ? (__half*)g_wqkvth : (__half*)g_wprojth;
    __shared__ float t[32][33];
    const int bx = blockIdx.x * 32;  // n
    const int by = blockIdx.y * 32;  // k
    const int x = threadIdx.x, y = threadIdx.y;  // 32 x 8
#pragma unroll
    for (int i = 0; i < 32; i += 8)
        t[y + i][x] = src[(size_t)(by + y + i) * N + bx + x];
    __syncthreads();
#pragma unroll
    for (int i = 0; i < 32; i += 8)
        dst[(size_t)(bx + y + i) * 512 + by + x] = __float2half_rn(t[x][y + i]);
}

// ===========================================================================
// FUSED QKV-GEMM + ATTENTION.
// Grid: 1024 CTAs (one per 2 batches = 128 token rows), 256 thr = 8 warps.
// For chunk c in 0..3 (4 heads each):
//   three sub-GEMMs (Q,K,V): Y = X(128x512) @ WqkvT rows [t*512+c*128 .. +128)
//   (R5 inner loop: 128x128 tile, warp 32x64, cp.async double-buffered)
//   results staged in SMEM (fp16, +bias); then 8 warps each run one
//   (batch-half, head) attention block: S=QK^T, gaussian mask, softmax,
//   P reused directly as A-fragments for P.V; O written to g_attnh.
// smem: A0@0 A1@18432 B0@36864 B1@55296 | Q@73728 K@108544 V@143360 (stride
// 272B) | Kss@178176 (16KB)  -> total 194560
// ===========================================================================
#define FOFF_A0 0
#define FOFF_A1 18432
#define FOFF_B0 36864
#define FOFF_B1 55296
#define FOFF_Q  73728
#define FOFF_K  108544
#define FOFF_V  143360
#define FOFF_KSS 178176
#define FSM_TOTAL 194560
#define STG_STRIDE 272   // bytes per 128-col fp16 staging row (256 + 16 pad)

__global__ void __launch_bounds__(256, 1) fused_qkv_attn_kernel(
    const float* __restrict__ b_qkv) {
    extern __shared__ char sm[];
    const uint32_t sb = smem_u32(sm);
    const int tid = threadIdx.x;
    const int lane = tid & 31;
    const int wid = tid >> 5;
    const int wm = wid >> 1;  // 0..3 -> GEMM m offset wm*32
    const int wn = wid & 1;   // 0..1 -> GEMM n offset wn*64
    const int bp = blockIdx.x;        // batch pair
    const size_t rowbase = (size_t)bp * 128;

    // ---- stage Kss into smem (4096 floats) ----
    float* kssf = (float*)(sm + FOFF_KSS);
    {
        const float4* src = (const float4*)g_Kss;
        float4* dst = (float4*)kssf;
#pragma unroll
        for (int it = 0; it < 4; ++it) dst[tid + it * 256] = src[tid + it * 256];
    }

    // loader mapping (R5): 8 lanes per 128B k-slice row
    const int lr = tid >> 3;       // 0..31
    const int lc = tid & 7;        // 16B chunk
    const char* Abase = (const char*)(g_xh + (rowbase + lr) * 512) + lc * 16;
    const uint32_t sA[2] = {sb + FOFF_A0, sb + FOFF_A1};
    const uint32_t sB[2] = {sb + FOFF_B0, sb + FOFF_B1};
    const uint32_t dstoff = (uint32_t)(lr * 144 + lc * 16);

    const int g = lane >> 2, t4 = lane & 3;
    const int iw = wid >> 2;   // attention: batch half 0..1
    const int hl = wid & 3;    // attention: local head 0..3

#pragma unroll 1
    for (int c = 0; c < 4; ++c) {
        // ================= three sub-GEMMs: t = 0(Q) 1(K) 2(V) ============
#pragma unroll 1
        for (int t = 0; t < 3; ++t) {
            const int ncol0 = t * 512 + c * 128;  // first output col (weight row)
            const char* Bbase =
                (const char*)(g_wqkvth + (size_t)(ncol0 + lr) * 512) + lc * 16;

            float acc[2][8][4];
#pragma unroll
            for (int mt = 0; mt < 2; ++mt)
#pragma unroll
                for (int nt = 0; nt < 8; ++nt)
#pragma unroll
                    for (int e = 0; e < 4; ++e) acc[mt][nt][e] = 0.f;

#define FLOAD(KT, BUF) do { \
    _Pragma("unroll") \
    for (int it = 0; it < 4; ++it) \
        cp16(sA[BUF] + dstoff + it * 32 * 144, Abase + (size_t)it * 32 * 1024 + (KT) * 128); \
    _Pragma("unroll") \
    for (int it = 0; it < 4; ++it) \
        cp16(sB[BUF] + dstoff + it * 32 * 144, Bbase + (size_t)it * 32 * 1024 + (KT) * 128); \
    CP_COMMIT(); \
} while (0)

            FLOAD(0, 0);
            FLOAD(1, 1);

#pragma unroll 1
            for (int kt = 0; kt < 8; ++kt) {
                const int buf = kt & 1;
                if (kt < 7) { CP_WAIT(1); } else { CP_WAIT(0); }
                __syncthreads();
#pragma unroll
                for (int kk = 0; kk < 4; ++kk) {
                    uint32_t a[2][4], b[4][4];
#pragma unroll
                    for (int mt = 0; mt < 2; ++mt) {
                        const uint32_t addr = sA[buf] +
                            (wm * 32 + mt * 16 + (lane & 15)) * 144 +
                            kk * 32 + (lane >> 4) * 16;
                        LDSM_X4(a[mt][0], a[mt][1], a[mt][2], a[mt][3], addr);
                    }
#pragma unroll
                    for (int nb = 0; nb < 4; ++nb) {
                        const uint32_t addr = sB[buf] +
                            (wn * 64 + nb * 16 + (lane & 15)) * 144 +
                            kk * 32 + (lane >> 4) * 16;
                        LDSM_X4(b[nb][0], b[nb][1], b[nb][2], b[nb][3], addr);
                    }
#pragma unroll
                    for (int mt = 0; mt < 2; ++mt)
#pragma unroll
                        for (int nt = 0; nt < 8; ++nt)
                            mma16816(acc[mt][nt], a[mt], b[nt >> 1][nt & 1],
                                     b[nt >> 1][2 + (nt & 1)]);
                }
                __syncthreads();
                if (kt + 2 < 8) FLOAD(kt + 2, buf);
            }
#undef FLOAD

            // epilogue: +bias, fp16, into staging t (warp-private region)
            char* st = sm + (t == 0 ? FOFF_Q : (t == 1 ? FOFF_K : FOFF_V));
#pragma unroll
            for (int mt = 0; mt < 2; ++mt) {
                const int r0 = wm * 32 + mt * 16 + g;
#pragma unroll
                for (int nt = 0; nt < 8; ++nt) {
                    const int c0 = wn * 64 + nt * 8 + 2 * t4;
                    const float2 bv = *(const float2*)(b_qkv + ncol0 + c0);
                    *(half2*)(st + r0 * STG_STRIDE + c0 * 2) =
                        __floats2half2_rn(acc[mt][nt][0] + bv.x,
                                          acc[mt][nt][1] + bv.y);
                    *(half2*)(st + (r0 + 8) * STG_STRIDE + c0 * 2) =
                        __floats2half2_rn(acc[mt][nt][2] + bv.x,
                                          acc[mt][nt][3] + bv.y);
                }
            }
        }
        __syncthreads();  // staging complete (also orders Kss on c==0)

        // ================= attention: one (iw, hl) block per warp =========
        {
            const uint32_t qst = sb + FOFF_Q;
            const uint32_t kst = sb + FOFF_K;
            const uint32_t vst = sb + FOFF_V;
            const uint32_t colb = (uint32_t)(hl * 64);  // byte offset of head cols

            // ---- S = Q K^T : 64 x 64, K=32 ----
            float s[4][8][4];
#pragma unroll
            for (int mt = 0; mt < 4; ++mt)
#pragma unroll
                for (int nt = 0; nt < 8; ++nt)
#pragma unroll
                    for (int e = 0; e < 4; ++e) s[mt][nt][e] = 0.f;

#pragma unroll
            for (int kk = 0; kk < 2; ++kk) {
                uint32_t aq[4][4];
#pragma unroll
                for (int mt = 0; mt < 4; ++mt)
                    LDSM_X4(aq[mt][0], aq[mt][1], aq[mt][2], aq[mt][3],
                            qst + (iw * 64 + mt * 16 + (lane & 15)) * STG_STRIDE +
                            colb + kk * 32 + (lane >> 4) * 16);
#pragma unroll
                for (int nb = 0; nb < 4; ++nb) {
                    uint32_t bk[4];
                    LDSM_X4(bk[0], bk[1], bk[2], bk[3],
                            kst + (iw * 64 + nb * 16 + (lane & 15)) * STG_STRIDE +
                            colb + kk * 32 + (lane >> 4) * 16);
#pragma unroll
                    for (int mt = 0; mt < 4; ++mt) {
                        mma16816(s[mt][nb * 2], aq[mt], bk[0], bk[2]);
                        mma16816(s[mt][nb * 2 + 1], aq[mt], bk[1], bk[3]);
                    }
                }
            }

            // ---- gaussian mask + softmax (per 16-row m-tile) ----
            float rA[4], rB[4];
#pragma unroll
            for (int mt = 0; mt < 4; ++mt) {
                const int iA = mt * 16 + g;      // local token row
                const int iB = iA + 8;
                float mA = -1e30f, mB = -1e30f;
#pragma unroll
                for (int nt = 0; nt < 8; ++nt) {
                    const int j0 = nt * 8 + 2 * t4;
                    const float2 kA = *(const float2*)&kssf[iA * 64 + j0];
                    const float2 kB = *(const float2*)&kssf[iB * 64 + j0];
                    s[mt][nt][0] *= kA.x;
                    s[mt][nt][1] *= kA.y;
                    s[mt][nt][2] *= kB.x;
                    s[mt][nt][3] *= kB.y;
                    mA = fmaxf(mA, fmaxf(s[mt][nt][0], s[mt][nt][1]));
                    mB = fmaxf(mB, fmaxf(s[mt][nt][2], s[mt][nt][3]));
                }
                mA = fmaxf(mA, __shfl_xor_sync(0xffffffffu, mA, 1));
                mA = fmaxf(mA, __shfl_xor_sync(0xffffffffu, mA, 2));
                mB = fmaxf(mB, __shfl_xor_sync(0xffffffffu, mB, 1));
                mB = fmaxf(mB, __shfl_xor_sync(0xffffffffu, mB, 2));
                float sA_ = 0.f, sB_ = 0.f;
#pragma unroll
                for (int nt = 0; nt < 8; ++nt) {
                    s[mt][nt][0] = __expf(s[mt][nt][0] - mA);
                    s[mt][nt][1] = __expf(s[mt][nt][1] - mA);
                    s[mt][nt][2] = __expf(s[mt][nt][2] - mB);
                    s[mt][nt][3] = __expf(s[mt][nt][3] - mB);
                    sA_ += s[mt][nt][0] + s[mt][nt][1];
                    sB_ += s[mt][nt][2] + s[mt][nt][3];
                }
                sA_ += __shfl_xor_sync(0xffffffffu, sA_, 1);
                sA_ += __shfl_xor_sync(0xffffffffu, sA_, 2);
                sB_ += __shfl_xor_sync(0xffffffffu, sB_, 1);
                sB_ += __shfl_xor_sync(0xffffffffu, sB_, 2);
                rA[mt] = 1.0f / sA_;
                rB[mt] = 1.0f / sB_;
            }

            // ---- O = P V : 64 x 32, K=64 (P from registers) ----
            float o[4][4][4];
#pragma unroll
            for (int mt = 0; mt < 4; ++mt)
#pragma unroll
                for (int nt = 0; nt < 4; ++nt)
#pragma unroll
                    for (int e = 0; e < 4; ++e) o[mt][nt][e] = 0.f;

#pragma unroll
            for (int kk = 0; kk < 4; ++kk) {
                uint32_t vb0[4], vb1[4];
                LDSM_X4_T(vb0[0], vb0[1], vb0[2], vb0[3],
                          vst + (iw * 64 + kk * 16 + (lane & 15)) * STG_STRIDE +
                          colb + (lane >> 4) * 16);
                LDSM_X4_T(vb1[0], vb1[1], vb1[2], vb1[3],
                          vst + (iw * 64 + kk * 16 + (lane & 15)) * STG_STRIDE +
                          colb + 32 + (lane >> 4) * 16);
#pragma unroll
                for (int mt = 0; mt < 4; ++mt) {
                    uint32_t a[4];
                    a[0] = pack_h2(s[mt][2 * kk][0] * rA[mt], s[mt][2 * kk][1] * rA[mt]);
                    a[1] = pack_h2(s[mt][2 * kk][2] * rB[mt], s[mt][2 * kk][3] * rB[mt]);
                    a[2] = pack_h2(s[mt][2 * kk + 1][0] * rA[mt],
                                   s[mt][2 * kk + 1][1] * rA[mt]);
                    a[3] = pack_h2(s[mt][2 * kk + 1][2] * rB[mt],
                                   s[mt][2 * kk + 1][3] * rB[mt]);
                    mma16816(o[mt][0], a, vb0[0], vb0[1]);
                    mma16816(o[mt][1], a, vb0[2], vb0[3]);
                    mma16816(o[mt][2], a, vb1[0], vb1[1]);
                    mma16816(o[mt][3], a, vb1[2], vb1[3]);
                }
            }

            // ---- store O to g_attnh ----
            const int gcol0 = (c * 4 + hl) * 32;
#pragma unroll
            for (int mt = 0; mt < 4; ++mt) {
                const size_t grow = rowbase + iw * 64 + mt * 16 + g;
#pragma unroll
                for (int nt = 0; nt < 4; ++nt) {
                    const int cc = gcol0 + nt * 8 + 2 * t4;
                    *(half2*)(g_attnh + grow * 512 + cc) =
                        __floats2half2_rn(o[mt][nt][0], o[mt][nt][1]);
                    *(half2*)(g_attnh + (grow + 8) * 512 + cc) =
                        __floats2half2_rn(o[mt][nt][2], o[mt][nt][3]);
                }
            }
        }
        // next chunk's first __syncthreads gates staging reuse
    }
}

// ---------------------------------------------------------------------------
// Proj GEMM (R5 config verbatim, MODE 1): out[M,512] = attnh @ wprojT + bias
// CTA 128x128, 256 thr (8 warps 4m x 2n, warp 32x64), occ 2.
// ---------------------------------------------------------------------------
#define GSM_TOTAL 73728

__global__ void __launch_bounds__(256, 2) proj_gemm_kernel(
    const float* __restrict__ bias, float* __restrict__ CoutF) {
    const __half* __restrict__ A = (const __half*)g_attnh;
    const __half* __restrict__ Bt = (const __half*)g_wprojth;

    extern __shared__ char sm[];
    const uint32_t sb = smem_u32(sm);
    const int tid = threadIdx.x;
    const int lane = tid & 31;
    const int wid = tid >> 5;
    const int wm = wid >> 1;  // 0..3
    const int wn = wid & 1;   // 0..1

    const int brow = blockIdx.y * 128;
    const int bcol = blockIdx.x * 128;

    const int lr = tid >> 3;
    const int lc = tid & 7;
    const char* Abase = (const char*)(A + (size_t)(brow + lr) * 512) + lc * 16;
    const char* Bbase = (const char*)(Bt + (size_t)(bcol + lr) * 512) + lc * 16;
    const uint32_t sA[2] = {sb + 0, sb + 36864};
    const uint32_t sB[2] = {sb + 18432, sb + 55296};
    const uint32_t dstoff = (uint32_t)(lr * 144 + lc * 16);

    float c[2][8][4];
#pragma unroll
    for (int mt = 0; mt < 2; ++mt)
#pragma unroll
        for (int nt = 0; nt < 8; ++nt)
#pragma unroll
            for (int e = 0; e < 4; ++e) c[mt][nt][e] = 0.f;

#define PLOAD(KT, BUF) do { \
    _Pragma("unroll") \
    for (int it = 0; it < 4; ++it) \
        cp16(sA[BUF] + dstoff + it * 32 * 144, Abase + (size_t)it * 32 * 1024 + (KT) * 128); \
    _Pragma("unroll") \
    for (int it = 0; it < 4; ++it) \
        cp16(sB[BUF] + dstoff + it * 32 * 144, Bbase + (size_t)it * 32 * 1024 + (KT) * 128); \
    CP_COMMIT(); \
} while (0)

    PLOAD(0, 0);
    PLOAD(1, 1);

#pragma unroll 1
    for (int kt = 0; kt < 8; ++kt) {
        const int buf = kt & 1;
        if (kt < 7) { CP_WAIT(1); } else { CP_WAIT(0); }
        __syncthreads();
#pragma unroll
        for (int kk = 0; kk < 4; ++kk) {
            uint32_t a[2][4], b[4][4];
#pragma unroll
            for (int mt = 0; mt < 2; ++mt) {
                const uint32_t addr = sA[buf] + (wm * 32 + mt * 16 + (lane & 15)) * 144 +
                                      kk * 32 + (lane >> 4) * 16;
                LDSM_X4(a[mt][0], a[mt][1], a[mt][2], a[mt][3], addr);
            }
#pragma unroll
            for (int nb = 0; nb < 4; ++nb) {
                const uint32_t addr = sB[buf] + (wn * 64 + nb * 16 + (lane & 15)) * 144 +
                                      kk * 32 + (lane >> 4) * 16;
                LDSM_X4(b[nb][0], b[nb][1], b[nb][2], b[nb][3], addr);
            }
#pragma unroll
            for (int mt = 0; mt < 2; ++mt)
#pragma unroll
                for (int nt = 0; nt < 8; ++nt)
                    mma16816(c[mt][nt], a[mt], b[nt >> 1][nt & 1],
                             b[nt >> 1][2 + (nt & 1)]);
        }
        __syncthreads();
        if (kt + 2 < 8) PLOAD(kt + 2, buf);
    }
#undef PLOAD

    // epilogue: stage fp32 in smem, coalesced fp32 store
    float* es = (float*)sm;  // 128 x 132
    const int g = lane >> 2, t4 = lane & 3;
#pragma unroll
    for (int mt = 0; mt < 2; ++mt) {
        const int r0 = wm * 32 + mt * 16 + g;
#pragma unroll
        for (int nt = 0; nt < 8; ++nt) {
            const int c0 = wn * 64 + nt * 8 + 2 * t4;
            *(float2*)&es[r0 * 132 + c0] = make_float2(c[mt][nt][0], c[mt][nt][1]);
            *(float2*)&es[(r0 + 8) * 132 + c0] = make_float2(c[mt][nt][2], c[mt][nt][3]);
        }
    }
    __syncthreads();

    const int cb = (tid & 31) * 4;
    const float4 bv = *(const float4*)(bias + bcol + cb);
#pragma unroll
    for (int it = 0; it < 16; ++it) {
        const int row = (tid >> 5) + it * 8;
        float4 o;
        o.x = es[row * 132 + cb + 0] + bv.x;
        o.y = es[row * 132 + cb + 1] + bv.y;
        o.z = es[row * 132 + cb + 2] + bv.z;
        o.w = es[row * 132 + cb + 3] + bv.w;
        *(float4*)(CoutF + (size_t)(brow + row) * DIM + bcol + cb) = o;
    }
}

// ---------------------------------------------------------------------------
// Launch
// ---------------------------------------------------------------------------
extern "C" void kernel_launch(void* const* d_in, const int* in_sizes, int n_in,
                              void* d_out, int out_size) {
    (void)in_sizes;
    (void)n_in;
    (void)out_size;
    const float* x = (const float*)d_in[0];
    const float* w_qkv = (const float*)d_in[1];
    const float* b_qkv = (const float*)d_in[2];
    const float* w_proj = (const float*)d_in[3];
    const float* b_proj = (const float*)d_in[4];
    float* out = (float*)d_out;

    cudaFuncSetAttribute(fused_qkv_attn_kernel,
                         cudaFuncAttributeMaxDynamicSharedMemorySize, FSM_TOTAL);
    cudaFuncSetAttribute(proj_gemm_kernel,
                         cudaFuncAttributeMaxDynamicSharedMemorySize, GSM_TOTAL);

    init_kss_kernel<<<1, 64>>>();
    cvt_x_kernel<<<MTOT * DIM / 8 / 256, 256>>>(x);
    transpose_cvt_kernel<0><<<dim3(QKV / 32, DIM / 32), dim3(32, 8)>>>(w_qkv);
    transpose_cvt_kernel<1><<<dim3(DIM / 32, DIM / 32), dim3(32, 8)>>>(w_proj);
    fused_qkv_attn_kernel<<<BATCH / 2, 256, FSM_TOTAL>>>(b_qkv);
    proj_gemm_kernel<<<dim3(DIM / 128, MTOT / 128), 256, GSM_TOTAL>>>(b_proj, out);
}

// round 8
// speedup vs baseline: 1.0684x; 1.0256x over previous
#include <cuda_runtime.h>
#include <cuda_fp16.h>
#include <cstdint>

#define BATCH 2048
#define NTOK 64
#define DIM 512
#define HEADS 16
#define QKV 1536
#define MTOT (BATCH * NTOK)      // 131072 rows

// ---------------------------------------------------------------------------
// Scratch (static __device__ globals; no allocations allowed)
// ---------------------------------------------------------------------------
__device__ __half g_xh[(size_t)MTOT * DIM];      // 134 MB: x in fp16
__device__ __half g_attnh[(size_t)MTOT * DIM];   // 134 MB: attention out (fp16)
__device__ __half g_wqkvth[QKV * DIM];           // w_qkv^T  [1536][512] fp16
__device__ __half g_wprojth[DIM * DIM];          // w_proj^T [512][512] fp16
__device__ float g_Kss[NTOK * NTOK];             // gaussian * softmax scale

// ---------------------------------------------------------------------------
// PTX helpers
// ---------------------------------------------------------------------------
__device__ __forceinline__ uint32_t smem_u32(const void* p) {
    uint32_t a;
    asm("{ .reg .u64 t; cvta.to.shared.u64 t, %1; cvt.u32.u64 %0, t; }"
        : "=r"(a) : "l"(p));
    return a;
}

__device__ __forceinline__ void cp16(uint32_t dst, const void* src) {
    asm volatile("cp.async.cg.shared.global [%0], [%1], 16;"
                 :: "r"(dst), "l"(src));
}
#define CP_COMMIT() asm volatile("cp.async.commit_group;")
#define CP_WAIT(N) asm volatile("cp.async.wait_group %0;" :: "n"(N))

#define LDSM_X4(R0, R1, R2, R3, ADDR) \
    asm volatile("ldmatrix.sync.aligned.m8n8.x4.shared.b16 {%0,%1,%2,%3}, [%4];" \
                 : "=r"(R0), "=r"(R1), "=r"(R2), "=r"(R3) : "r"(ADDR))
#define LDSM_X4_T(R0, R1, R2, R3, ADDR) \
    asm volatile("ldmatrix.sync.aligned.m8n8.x4.trans.shared.b16 {%0,%1,%2,%3}, [%4];" \
                 : "=r"(R0), "=r"(R1), "=r"(R2), "=r"(R3) : "r"(ADDR))

__device__ __forceinline__ void mma16816(float c[4], const uint32_t a[4],
                                         uint32_t b0, uint32_t b1) {
    asm volatile(
        "mma.sync.aligned.m16n8k16.row.col.f32.f16.f16.f32 "
        "{%0,%1,%2,%3}, {%4,%5,%6,%7}, {%8,%9}, {%0,%1,%2,%3};"
        : "+f"(c[0]), "+f"(c[1]), "+f"(c[2]), "+f"(c[3])
        : "r"(a[0]), "r"(a[1]), "r"(a[2]), "r"(a[3]), "r"(b0), "r"(b1));
}

__device__ __forceinline__ uint32_t pack_h2(float x, float y) {
    half2 h = __floats2half2_rn(x, y);
    return *(uint32_t*)&h;
}

// ---------------------------------------------------------------------------
// Kss precompute: row-normalised gaussian * HEAD_DIM^-0.5
// ---------------------------------------------------------------------------
__global__ void init_kss_kernel() {
    const int i = threadIdx.x;  // 0..63
    const float yi = (float)(i >> 3), xi = (float)(i & 7);
    const float inv2s2 = 1.0f / (2.0f * 0.39f * 0.39f);
    float row[64];
    float s = 0.f;
#pragma unroll
    for (int j = 0; j < 64; ++j) {
        float dy = yi - (float)(j >> 3);
        float dx = xi - (float)(j & 7);
        float e = __expf(-(dy * dy + dx * dx) * inv2s2);
        row[j] = e;
        s += e;
    }
    const float inv = 0.17677669529663688f / s;  // scale / rowsum
#pragma unroll
    for (int j = 0; j < 64; ++j) g_Kss[i * 64 + j] = row[j] * inv;
}

// ---------------------------------------------------------------------------
// x fp32 -> fp16
// ---------------------------------------------------------------------------
__global__ void cvt_x_kernel(const float* __restrict__ x) {
    const size_t i = ((size_t)blockIdx.x * 256 + threadIdx.x) * 8;
    float4 a = *(const float4*)(x + i);
    float4 b = *(const float4*)(x + i + 4);
    __half h[8];
    h[0] = __float2half_rn(a.x); h[1] = __float2half_rn(a.y);
    h[2] = __float2half_rn(a.z); h[3] = __float2half_rn(a.w);
    h[4] = __float2half_rn(b.x); h[5] = __float2half_rn(b.y);
    h[6] = __float2half_rn(b.z); h[7] = __float2half_rn(b.w);
    *(uint4*)(&g_xh[i]) = *(uint4*)h;
}

// ---------------------------------------------------------------------------
// Weight transpose + fp16 convert: dst[n][k] = h(src[k][n]); K = 512
// ---------------------------------------------------------------------------
template <int MODE>
__global__ void transpose_cvt_kernel(const float* __restrict__ src) {
    constexpr int N = (MODE == 0) ? QKV : DIM;
    __half* __restrict__ dst = (MODE == 0) ? (__half*)g_wqkvth : (__half*)g_wprojth;
    __shared__ float t[32][33];
    const int bx = blockIdx.x * 32;  // n
    const int by = blockIdx.y * 32;  // k
    const int x = threadIdx.x, y = threadIdx.y;  // 32 x 8
#pragma unroll
    for (int i = 0; i < 32; i += 8)
        t[y + i][x] = src[(size_t)(by + y + i) * N + bx + x];
    __syncthreads();
#pragma unroll
    for (int i = 0; i < 32; i += 8)
        dst[(size_t)(bx + y + i) * 512 + by + x] = __float2half_rn(t[x][y + i]);
}

// ===========================================================================
// FUSED QKV-GEMM + ATTENTION (3-stage pipeline, continuous load stream).
// Grid: 1024 CTAs (one per 2 batches = 128 token rows), 256 thr = 8 warps.
// 96 global k-tiles: gl -> chunk cc=gl/24, t=(gl/8)%3 (Q/K/V), kt=gl&7.
// One __syncthreads per tile; loads always 2 tiles ahead (crossing sub-GEMM
// and chunk boundaries, so attention overlaps the next chunk's loads).
// smem: 3 stages x (A 18432 + B 18432) @0 | Q@110592 K@145408 V@180224
// (stride 272B)  -> total 215040. Kss read from gmem (L2-hot).
// ===========================================================================
#define FOFF_Q  110592
#define FOFF_K  145408
#define FOFF_V  180224
#define FSM_TOTAL 215040
#define STG_STRIDE 272   // bytes per 128-col fp16 staging row (256 + 16 pad)

__global__ void __launch_bounds__(256, 1) fused_qkv_attn_kernel(
    const float* __restrict__ b_qkv) {
    extern __shared__ char sm[];
    const uint32_t sb = smem_u32(sm);
    const int tid = threadIdx.x;
    const int lane = tid & 31;
    const int wid = tid >> 5;
    const int wm = wid >> 1;  // 0..3 -> GEMM m offset wm*32
    const int wn = wid & 1;   // 0..1 -> GEMM n offset wn*64
    const int bp = blockIdx.x;        // batch pair
    const size_t rowbase = (size_t)bp * 128;

    // loader mapping: 8 lanes per 128B k-slice row
    const int lr = tid >> 3;       // 0..31
    const int lc = tid & 7;        // 16B chunk
    const char* Abase = (const char*)(g_xh + (rowbase + lr) * 512) + lc * 16;
    const uint32_t dstoff = (uint32_t)(lr * 144 + lc * 16);

    const int g = lane >> 2, t4 = lane & 3;
    const int iw = wid >> 2;   // attention: batch half 0..1
    const int hl = wid & 3;    // attention: local head 0..3

    // issue one k-tile load (A + B) for global load index gl into stage gl%3
#define ISSUE_LOAD(GL) do { \
    const int _gl = (GL); \
    const int _kt = _gl & 7; \
    const int _t = (_gl >> 3) % 3; \
    const int _cc = _gl / 24; \
    const int _col0 = _t * 512 + _cc * 128; \
    const uint32_t _buf = sb + (uint32_t)(_gl % 3) * 36864u; \
    const char* _Bb = (const char*)(g_wqkvth + (size_t)(_col0 + lr) * 512) + \
                      lc * 16 + _kt * 128; \
    _Pragma("unroll") \
    for (int it = 0; it < 4; ++it) \
        cp16(_buf + dstoff + it * 32 * 144, \
             Abase + (size_t)it * 32 * 1024 + _kt * 128); \
    _Pragma("unroll") \
    for (int it = 0; it < 4; ++it) \
        cp16(_buf + 18432 + dstoff + it * 32 * 144, _Bb + (size_t)it * 32 * 1024); \
    CP_COMMIT(); \
} while (0)

    ISSUE_LOAD(0);
    ISSUE_LOAD(1);

    int gi = 0;
#pragma unroll 1
    for (int c = 0; c < 4; ++c) {
        float acc[2][8][4];
#pragma unroll
        for (int mt = 0; mt < 2; ++mt)
#pragma unroll
            for (int nt = 0; nt < 8; ++nt)
#pragma unroll
                for (int e = 0; e < 4; ++e) acc[mt][nt][e] = 0.f;

#pragma unroll 1
        for (int i = 0; i < 24; ++i, ++gi) {
            CP_WAIT(1);
            __syncthreads();
            if (gi + 2 < 96) ISSUE_LOAD(gi + 2);
            const uint32_t bufA = sb + (uint32_t)(gi % 3) * 36864u;
            const uint32_t bufB = bufA + 18432u;
#pragma unroll
            for (int kk = 0; kk < 4; ++kk) {
                uint32_t a[2][4], b[4][4];
#pragma unroll
                for (int mt = 0; mt < 2; ++mt) {
                    const uint32_t addr = bufA +
                        (wm * 32 + mt * 16 + (lane & 15)) * 144 +
                        kk * 32 + (lane >> 4) * 16;
                    LDSM_X4(a[mt][0], a[mt][1], a[mt][2], a[mt][3], addr);
                }
#pragma unroll
                for (int nb = 0; nb < 4; ++nb) {
                    const uint32_t addr = bufB +
                        (wn * 64 + nb * 16 + (lane & 15)) * 144 +
                        kk * 32 + (lane >> 4) * 16;
                    LDSM_X4(b[nb][0], b[nb][1], b[nb][2], b[nb][3], addr);
                }
#pragma unroll
                for (int mt = 0; mt < 2; ++mt)
#pragma unroll
                    for (int nt = 0; nt < 8; ++nt)
                        mma16816(acc[mt][nt], a[mt], b[nt >> 1][nt & 1],
                                 b[nt >> 1][2 + (nt & 1)]);
            }
            // end of a Q/K/V group: epilogue into staging, reset accumulators
            if ((i & 7) == 7) {
                const int t = i >> 3;
                const int ncol0 = t * 512 + c * 128;
                char* st = sm + (t == 0 ? FOFF_Q : (t == 1 ? FOFF_K : FOFF_V));
#pragma unroll
                for (int mt = 0; mt < 2; ++mt) {
                    const int r0 = wm * 32 + mt * 16 + g;
#pragma unroll
                    for (int nt = 0; nt < 8; ++nt) {
                        const int c0 = wn * 64 + nt * 8 + 2 * t4;
                        const float2 bv = *(const float2*)(b_qkv + ncol0 + c0);
                        *(half2*)(st + r0 * STG_STRIDE + c0 * 2) =
                            __floats2half2_rn(acc[mt][nt][0] + bv.x,
                                              acc[mt][nt][1] + bv.y);
                        *(half2*)(st + (r0 + 8) * STG_STRIDE + c0 * 2) =
                            __floats2half2_rn(acc[mt][nt][2] + bv.x,
                                              acc[mt][nt][3] + bv.y);
                        acc[mt][nt][0] = 0.f;
                        acc[mt][nt][1] = 0.f;
                        acc[mt][nt][2] = 0.f;
                        acc[mt][nt][3] = 0.f;
                    }
                }
            }
        }
        __syncthreads();  // staging complete (next chunk's loads in flight)

        // ================= attention: one (iw, hl) block per warp =========
        {
            const uint32_t qst = sb + FOFF_Q;
            const uint32_t kst = sb + FOFF_K;
            const uint32_t vst = sb + FOFF_V;
            const uint32_t colb = (uint32_t)(hl * 64);  // byte offset of head cols

            // ---- S = Q K^T : 64 x 64, K=32 ----
            float s[4][8][4];
#pragma unroll
            for (int mt = 0; mt < 4; ++mt)
#pragma unroll
                for (int nt = 0; nt < 8; ++nt)
#pragma unroll
                    for (int e = 0; e < 4; ++e) s[mt][nt][e] = 0.f;

#pragma unroll
            for (int kk = 0; kk < 2; ++kk) {
                uint32_t aq[4][4];
#pragma unroll
                for (int mt = 0; mt < 4; ++mt)
                    LDSM_X4(aq[mt][0], aq[mt][1], aq[mt][2], aq[mt][3],
                            qst + (iw * 64 + mt * 16 + (lane & 15)) * STG_STRIDE +
                            colb + kk * 32 + (lane >> 4) * 16);
#pragma unroll
                for (int nb = 0; nb < 4; ++nb) {
                    uint32_t bk[4];
                    LDSM_X4(bk[0], bk[1], bk[2], bk[3],
                            kst + (iw * 64 + nb * 16 + (lane & 15)) * STG_STRIDE +
                            colb + kk * 32 + (lane >> 4) * 16);
#pragma unroll
                    for (int mt = 0; mt < 4; ++mt) {
                        mma16816(s[mt][nb * 2], aq[mt], bk[0], bk[2]);
                        mma16816(s[mt][nb * 2 + 1], aq[mt], bk[1], bk[3]);
                    }
                }
            }

            // ---- gaussian mask + softmax (per 16-row m-tile) ----
            float rA[4], rB[4];
#pragma unroll
            for (int mt = 0; mt < 4; ++mt) {
                const int iA = mt * 16 + g;      // local token row
                const int iB = iA + 8;
                float mA = -1e30f, mB = -1e30f;
#pragma unroll
                for (int nt = 0; nt < 8; ++nt) {
                    const int j0 = nt * 8 + 2 * t4;
                    const float2 kA = *(const float2*)&g_Kss[iA * 64 + j0];
                    const float2 kB = *(const float2*)&g_Kss[iB * 64 + j0];
                    s[mt][nt][0] *= kA.x;
                    s[mt][nt][1] *= kA.y;
                    s[mt][nt][2] *= kB.x;
                    s[mt][nt][3] *= kB.y;
                    mA = fmaxf(mA, fmaxf(s[mt][nt][0], s[mt][nt][1]));
                    mB = fmaxf(mB, fmaxf(s[mt][nt][2], s[mt][nt][3]));
                }
                mA = fmaxf(mA, __shfl_xor_sync(0xffffffffu, mA, 1));
                mA = fmaxf(mA, __shfl_xor_sync(0xffffffffu, mA, 2));
                mB = fmaxf(mB, __shfl_xor_sync(0xffffffffu, mB, 1));
                mB = fmaxf(mB, __shfl_xor_sync(0xffffffffu, mB, 2));
                float sA_ = 0.f, sB_ = 0.f;
#pragma unroll
                for (int nt = 0; nt < 8; ++nt) {
                    s[mt][nt][0] = __expf(s[mt][nt][0] - mA);
                    s[mt][nt][1] = __expf(s[mt][nt][1] - mA);
                    s[mt][nt][2] = __expf(s[mt][nt][2] - mB);
                    s[mt][nt][3] = __expf(s[mt][nt][3] - mB);
                    sA_ += s[mt][nt][0] + s[mt][nt][1];
                    sB_ += s[mt][nt][2] + s[mt][nt][3];
                }
                sA_ += __shfl_xor_sync(0xffffffffu, sA_, 1);
                sA_ += __shfl_xor_sync(0xffffffffu, sA_, 2);
                sB_ += __shfl_xor_sync(0xffffffffu, sB_, 1);
                sB_ += __shfl_xor_sync(0xffffffffu, sB_, 2);
                rA[mt] = 1.0f / sA_;
                rB[mt] = 1.0f / sB_;
            }

            // ---- O = P V : 64 x 32, K=64 (P from registers) ----
            float o[4][4][4];
#pragma unroll
            for (int mt = 0; mt < 4; ++mt)
#pragma unroll
                for (int nt = 0; nt < 4; ++nt)
#pragma unroll
                    for (int e = 0; e < 4; ++e) o[mt][nt][e] = 0.f;

#pragma unroll
            for (int kk = 0; kk < 4; ++kk) {
                uint32_t vb0[4], vb1[4];
                LDSM_X4_T(vb0[0], vb0[1], vb0[2], vb0[3],
                          vst + (iw * 64 + kk * 16 + (lane & 15)) * STG_STRIDE +
                          colb + (lane >> 4) * 16);
                LDSM_X4_T(vb1[0], vb1[1], vb1[2], vb1[3],
                          vst + (iw * 64 + kk * 16 + (lane & 15)) * STG_STRIDE +
                          colb + 32 + (lane >> 4) * 16);
#pragma unroll
                for (int mt = 0; mt < 4; ++mt) {
                    uint32_t a[4];
                    a[0] = pack_h2(s[mt][2 * kk][0] * rA[mt], s[mt][2 * kk][1] * rA[mt]);
                    a[1] = pack_h2(s[mt][2 * kk][2] * rB[mt], s[mt][2 * kk][3] * rB[mt]);
                    a[2] = pack_h2(s[mt][2 * kk + 1][0] * rA[mt],
                                   s[mt][2 * kk + 1][1] * rA[mt]);
                    a[3] = pack_h2(s[mt][2 * kk + 1][2] * rB[mt],
                                   s[mt][2 * kk + 1][3] * rB[mt]);
                    mma16816(o[mt][0], a, vb0[0], vb0[1]);
                    mma16816(o[mt][1], a, vb0[2], vb0[3]);
                    mma16816(o[mt][2], a, vb1[0], vb1[1]);
                    mma16816(o[mt][3], a, vb1[2], vb1[3]);
                }
            }

            // ---- store O to g_attnh ----
            const int gcol0 = (c * 4 + hl) * 32;
#pragma unroll
            for (int mt = 0; mt < 4; ++mt) {
                const size_t grow = rowbase + iw * 64 + mt * 16 + g;
#pragma unroll
                for (int nt = 0; nt < 4; ++nt) {
                    const int cc = gcol0 + nt * 8 + 2 * t4;
                    *(half2*)(g_attnh + grow * 512 + cc) =
                        __floats2half2_rn(o[mt][nt][0], o[mt][nt][1]);
                    *(half2*)(g_attnh + (grow + 8) * 512 + cc) =
                        __floats2half2_rn(o[mt][nt][2], o[mt][nt][3]);
                }
            }
        }
        // next chunk's first __syncthreads gates staging reuse
    }
#undef ISSUE_LOAD
}

// ---------------------------------------------------------------------------
// Proj GEMM (R5 config verbatim): out[M,512] = attnh @ wprojT + bias
// CTA 128x128, 256 thr (8 warps 4m x 2n, warp 32x64), occ 2.
// ---------------------------------------------------------------------------
#define GSM_TOTAL 73728

__global__ void __launch_bounds__(256, 2) proj_gemm_kernel(
    const float* __restrict__ bias, float* __restrict__ CoutF) {
    const __half* __restrict__ A = (const __half*)g_attnh;
    const __half* __restrict__ Bt = (const __half*)g_wprojth;

    extern __shared__ char sm[];
    const uint32_t sb = smem_u32(sm);
    const int tid = threadIdx.x;
    const int lane = tid & 31;
    const int wid = tid >> 5;
    const int wm = wid >> 1;  // 0..3
    const int wn = wid & 1;   // 0..1

    const int brow = blockIdx.y * 128;
    const int bcol = blockIdx.x * 128;

    const int lr = tid >> 3;
    const int lc = tid & 7;
    const char* Abase = (const char*)(A + (size_t)(brow + lr) * 512) + lc * 16;
    const char* Bbase = (const char*)(Bt + (size_t)(bcol + lr) * 512) + lc * 16;
    const uint32_t sA[2] = {sb + 0, sb + 36864};
    const uint32_t sB[2] = {sb + 18432, sb + 55296};
    const uint32_t dstoff = (uint32_t)(lr * 144 + lc * 16);

    float c[2][8][4];
#pragma unroll
    for (int mt = 0; mt < 2; ++mt)
#pragma unroll
        for (int nt = 0; nt < 8; ++nt)
#pragma unroll
            for (int e = 0; e < 4; ++e) c[mt][nt][e] = 0.f;

#define PLOAD(KT, BUF) do { \
    _Pragma("unroll") \
    for (int it = 0; it < 4; ++it) \
        cp16(sA[BUF] + dstoff + it * 32 * 144, Abase + (size_t)it * 32 * 1024 + (KT) * 128); \
    _Pragma("unroll") \
    for (int it = 0; it < 4; ++it) \
        cp16(sB[BUF] + dstoff + it * 32 * 144, Bbase + (size_t)it * 32 * 1024 + (KT) * 128); \
    CP_COMMIT(); \
} while (0)

    PLOAD(0, 0);
    PLOAD(1, 1);

#pragma unroll 1
    for (int kt = 0; kt < 8; ++kt) {
        const int buf = kt & 1;
        if (kt < 7) { CP_WAIT(1); } else { CP_WAIT(0); }
        __syncthreads();
#pragma unroll
        for (int kk = 0; kk < 4; ++kk) {
            uint32_t a[2][4], b[4][4];
#pragma unroll
            for (int mt = 0; mt < 2; ++mt) {
                const uint32_t addr = sA[buf] + (wm * 32 + mt * 16 + (lane & 15)) * 144 +
                                      kk * 32 + (lane >> 4) * 16;
                LDSM_X4(a[mt][0], a[mt][1], a[mt][2], a[mt][3], addr);
            }
#pragma unroll
            for (int nb = 0; nb < 4; ++nb) {
                const uint32_t addr = sB[buf] + (wn * 64 + nb * 16 + (lane & 15)) * 144 +
                                      kk * 32 + (lane >> 4) * 16;
                LDSM_X4(b[nb][0], b[nb][1], b[nb][2], b[nb][3], addr);
            }
#pragma unroll
            for (int mt = 0; mt < 2; ++mt)
#pragma unroll
                for (int nt = 0; nt < 8; ++nt)
                    mma16816(c[mt][nt], a[mt], b[nt >> 1][nt & 1],
                             b[nt >> 1][2 + (nt & 1)]);
        }
        __syncthreads();
        if (kt + 2 < 8) PLOAD(kt + 2, buf);
    }
#undef PLOAD

    // epilogue: stage fp32 in smem, coalesced fp32 store
    float* es = (float*)sm;  // 128 x 132
    const int g = lane >> 2, t4 = lane & 3;
#pragma unroll
    for (int mt = 0; mt < 2; ++mt) {
        const int r0 = wm * 32 + mt * 16 + g;
#pragma unroll
        for (int nt = 0; nt < 8; ++nt) {
            const int c0 = wn * 64 + nt * 8 + 2 * t4;
            *(float2*)&es[r0 * 132 + c0] = make_float2(c[mt][nt][0], c[mt][nt][1]);
            *(float2*)&es[(r0 + 8) * 132 + c0] = make_float2(c[mt][nt][2], c[mt][nt][3]);
        }
    }
    __syncthreads();

    const int cb = (tid & 31) * 4;
    const float4 bv = *(const float4*)(bias + bcol + cb);
#pragma unroll
    for (int it = 0; it < 16; ++it) {
        const int row = (tid >> 5) + it * 8;
        float4 o;
        o.x = es[row * 132 + cb + 0] + bv.x;
        o.y = es[row * 132 + cb + 1] + bv.y;
        o.z = es[row * 132 + cb + 2] + bv.z;
        o.w = es[row * 132 + cb + 3] + bv.w;
        *(float4*)(CoutF + (size_t)(brow + row) * DIM + bcol + cb) = o;
    }
}

// ---------------------------------------------------------------------------
// Launch
// ---------------------------------------------------------------------------
extern "C" void kernel_launch(void* const* d_in, const int* in_sizes, int n_in,
                              void* d_out, int out_size) {
    (void)in_sizes;
    (void)n_in;
    (void)out_size;
    const float* x = (const float*)d_in[0];
    const float* w_qkv = (const float*)d_in[1];
    const float* b_qkv = (const float*)d_in[2];
    const float* w_proj = (const float*)d_in[3];
    const float* b_proj = (const float*)d_in[4];
    float* out = (float*)d_out;

    cudaFuncSetAttribute(fused_qkv_attn_kernel,
                         cudaFuncAttributeMaxDynamicSharedMemorySize, FSM_TOTAL);
    cudaFuncSetAttribute(proj_gemm_kernel,
                         cudaFuncAttributeMaxDynamicSharedMemorySize, GSM_TOTAL);

    init_kss_kernel<<<1, 64>>>();
    cvt_x_kernel<<<MTOT * DIM / 8 / 256, 256>>>(x);
    transpose_cvt_kernel<0><<<dim3(QKV / 32, DIM / 32), dim3(32, 8)>>>(w_qkv);
    transpose_cvt_kernel<1><<<dim3(DIM / 32, DIM / 32), dim3(32, 8)>>>(w_proj);
    fused_qkv_attn_kernel<<<BATCH / 2, 256, FSM_TOTAL>>>(b_qkv);
    proj_gemm_kernel<<<dim3(DIM / 128, MTOT / 128), 256, GSM_TOTAL>>>(b_proj, out);
}